// round 3
// baseline (speedup 1.0000x reference)
#include <cuda_runtime.h>
#include <math.h>

#define BATCH 16
#define CH    128
#define HS    32
#define LFLAT 1024
#define KM    1152
#define NCONV 4096

__device__ float g_fd[BATCH*CH*HS*HS];
__device__ float g_bd[BATCH*CH*HS*HS];
__device__ float g_ssum[BATCH*LFLAT];
__device__ float g_rnorm[BATCH*LFLAT];
__device__ float g_A[BATCH*KM*LFLAT];
__device__ float g_Bm[BATCH*KM*LFLAT];
__device__ float g_y1[BATCH*LFLAT*LFLAT];
__device__ float g_y2[BATCH*LFLAT*LFLAT];
__device__ float g_bT[BATCH*64*64*CH];
__device__ float g_att[BATCH*CH*NCONV];
__device__ float g_im[BATCH*KM*NCONV];
__device__ float g_h[BATCH*CH*NCONV];
__device__ float g_Wt[KM*CH];

__device__ __forceinline__ float eluf(float v) { return v > 0.f ? v : expm1f(v); }

// 1) downsample f,b -> fd,bd (x[:,:,::2,::2])
__global__ void k_downsample(const float* __restrict__ f, const float* __restrict__ b) {
    int i = blockIdx.x * blockDim.x + threadIdx.x;
    if (i >= BATCH*CH*HS*HS) return;
    int x = i & 31, y = (i >> 5) & 31, cb = i >> 10;
    int src = (cb << 12) + (y << 7) + (x << 1);
    g_fd[i] = f[src];
    g_bd[i] = b[src];
}

// 2) channel square-sum of bd per pixel
__global__ void k_ssum() {
    int i = blockIdx.x * blockDim.x + threadIdx.x;
    if (i >= BATCH*LFLAT) return;
    int bb = i >> 10, s = i & 1023;
    const float* p = g_bd + ((long)bb * CH << 10) + s;
    float a0=0, a1=0, a2=0, a3=0;
    for (int c = 0; c < CH; c += 4) {
        float v0 = p[(long)c << 10], v1 = p[(long)(c+1) << 10];
        float v2 = p[(long)(c+2) << 10], v3 = p[(long)(c+3) << 10];
        a0 += v0*v0; a1 += v1*v1; a2 += v2*v2; a3 += v3*v3;
    }
    g_ssum[i] = (a0 + a1) + (a2 + a3);
}

// 3) 3x3 patch norms -> reciprocal of max(norm, 1e-4)
__global__ void k_norm() {
    int i = blockIdx.x * blockDim.x + threadIdx.x;
    if (i >= BATCH*LFLAT) return;
    int bb = i >> 10, p = i & 1023;
    int hb = p >> 5, wb = p & 31;
    float s = 0.f;
    #pragma unroll
    for (int di = -1; di <= 1; di++)
        #pragma unroll
        for (int dj = -1; dj <= 1; dj++) {
            int y = hb + di, x = wb + dj;
            if ((unsigned)y < 32u && (unsigned)x < 32u)
                s += g_ssum[(bb << 10) + (y << 5) + x];
        }
    g_rnorm[i] = 1.f / fmaxf(sqrtf(s), 1e-4f);
}

// 4) im2col 32x32 k=3 pad=1 : dst[b][k=(c,i,j)][p], optionally * rnorm[p]
__global__ void k_im2col_s(const float* __restrict__ src, float* __restrict__ dst, int use_norm) {
    int i = blockIdx.x * blockDim.x + threadIdx.x;
    if (i >= BATCH*KM*LFLAT) return;
    int p  = i & 1023;
    int r  = i >> 10;
    int k  = r % KM;
    int bb = r / KM;
    int c  = k / 9, t = k - c * 9;
    int di = t / 3 - 1, dj = t - (t / 3) * 3 - 1;
    int y = (p >> 5) + di, x = (p & 31) + dj;
    float v = 0.f;
    if ((unsigned)y < 32u && (unsigned)x < 32u)
        v = src[(((long)bb * CH + c) << 10) + (y << 5) + x];
    if (use_norm) v *= g_rnorm[(bb << 10) + p];
    dst[i] = v;
}

// 5) im2col 64x64 k=3 pad=1
__global__ void k_im2col_l(const float* __restrict__ src, float* __restrict__ dst) {
    int i = blockIdx.x * blockDim.x + threadIdx.x;
    if (i >= BATCH*KM*NCONV) return;
    int n  = i & 4095;
    int r  = i >> 12;
    int k  = r % KM;
    int bb = r / KM;
    int c  = k / 9, t = k - c * 9;
    int di = t / 3 - 1, dj = t - (t / 3) * 3 - 1;
    int u = (n >> 6) + di, v = (n & 63) + dj;
    float val = 0.f;
    if ((unsigned)u < 64u && (unsigned)v < 64u)
        val = src[(((long)bb * CH + c) << 12) + (u << 6) + v];
    dst[i] = val;
}

// 6) SGEMM: C[m][n] = sum_k A[k][m]*B[k][n]. 128x128x8, 256 thr, 8x8/thread.
//    EPI 0: plain store. EPI 1: +bias[m], ELU.
template <int EPI>
__global__ __launch_bounds__(256)
void k_gemm(const float* __restrict__ A, const float* __restrict__ B,
            const float* __restrict__ bias, float* __restrict__ C,
            int M, int N, int K, long aB, long bB, long cB) {
    __shared__ float As[8][128];
    __shared__ float Bs[8][128];
    const int bb = blockIdx.z;
    const float* Ag = A + (long)bb * aB;
    const float* Bg = B + (long)bb * bB;
    float* Cg = C + (long)bb * cB;
    const int m0 = blockIdx.y << 7, n0 = blockIdx.x << 7;
    const int tid = threadIdx.x;
    const int lr = tid >> 5, lc = (tid & 31) << 2;
    const int tx = tid & 15, ty = tid >> 4;

    float4 ar = *(const float4*)(Ag + (long)lr * M + m0 + lc);
    float4 br = *(const float4*)(Bg + (long)lr * N + n0 + lc);

    float acc[8][8];
    #pragma unroll
    for (int i = 0; i < 8; i++)
        #pragma unroll
        for (int j = 0; j < 8; j++) acc[i][j] = 0.f;

    for (int k0 = 0; k0 < K; k0 += 8) {
        *(float4*)&As[lr][lc] = ar;
        *(float4*)&Bs[lr][lc] = br;
        __syncthreads();
        if (k0 + 8 < K) {
            ar = *(const float4*)(Ag + (long)(k0 + 8 + lr) * M + m0 + lc);
            br = *(const float4*)(Bg + (long)(k0 + 8 + lr) * N + n0 + lc);
        }
        #pragma unroll
        for (int kk = 0; kk < 8; kk++) {
            float a[8], bv[8];
            *(float4*)&a[0]  = *(const float4*)&As[kk][ty << 2];
            *(float4*)&a[4]  = *(const float4*)&As[kk][64 + (ty << 2)];
            *(float4*)&bv[0] = *(const float4*)&Bs[kk][tx << 2];
            *(float4*)&bv[4] = *(const float4*)&Bs[kk][64 + (tx << 2)];
            #pragma unroll
            for (int i = 0; i < 8; i++)
                #pragma unroll
                for (int j = 0; j < 8; j++) acc[i][j] += a[i] * bv[j];
        }
        __syncthreads();
    }

    #pragma unroll
    for (int i = 0; i < 8; i++) {
        int m = m0 + ((i >> 2) << 6) + (ty << 2) + (i & 3);
        float bv = (EPI == 1) ? bias[m] : 0.f;
        float4 v0, v1;
        v0.x = acc[i][0]; v0.y = acc[i][1]; v0.z = acc[i][2]; v0.w = acc[i][3];
        v1.x = acc[i][4]; v1.y = acc[i][5]; v1.z = acc[i][6]; v1.w = acc[i][7];
        if (EPI == 1) {
            v0.x = eluf(v0.x + bv); v0.y = eluf(v0.y + bv);
            v0.z = eluf(v0.z + bv); v0.w = eluf(v0.w + bv);
            v1.x = eluf(v1.x + bv); v1.y = eluf(v1.y + bv);
            v1.z = eluf(v1.z + bv); v1.w = eluf(v1.w + bv);
        }
        *(float4*)(Cg + (long)m * N + n0 + (tx << 2))      = v0;
        *(float4*)(Cg + (long)m * N + n0 + 64 + (tx << 2)) = v1;
    }
}

// 7) fuse pass 1: out[l][m] = sum_{d=-1..1} in[l+d][m+d] on flat 1024x1024
__global__ void k_fuse1(const float* __restrict__ in, float* __restrict__ out) {
    long i = (long)blockIdx.x * blockDim.x + threadIdx.x;
    if (i >= (long)BATCH*LFLAT*LFLAT) return;
    int m = i & 1023, l = (i >> 10) & 1023, bb = i >> 20;
    const float* T = in + ((long)bb << 20);
    float v = T[((long)l << 10) + m];
    if (l > 0    && m > 0)    v += T[((long)(l - 1) << 10) + (m - 1)];
    if (l < 1023 && m < 1023) v += T[((long)(l + 1) << 10) + (m + 1)];
    out[i] = v;
}

// 8) fuse pass 2: same diagonal pass in transposed (wb*32+hb) indexing
__global__ void k_fuse2(const float* __restrict__ in, float* __restrict__ out) {
    long i = (long)blockIdx.x * blockDim.x + threadIdx.x;
    if (i >= (long)BATCH*LFLAT*LFLAT) return;
    int m = i & 1023, l = (i >> 10) & 1023, bb = i >> 20;
    const float* T = in + ((long)bb << 20);
    int lt = ((l & 31) << 5) + (l >> 5);
    int mt = ((m & 31) << 5) + (m >> 5);
    float acc = 0.f;
    #pragma unroll
    for (int d = -1; d <= 1; d++) {
        int v = lt + d, w = mt + d;
        if ((unsigned)v < 1024u && (unsigned)w < 1024u) {
            int row = ((v & 31) << 5) + (v >> 5);
            int col = ((w & 31) << 5) + (w >> 5);
            acc += T[((long)row << 10) + col];
        }
    }
    out[i] = acc;
}

// 9) softmax over patch axis p (rows of [p][q]), scale 10
__global__ __launch_bounds__(256) void k_softmax(const float* __restrict__ S, float* __restrict__ P) {
    __shared__ float red[8][32];
    __shared__ float bcast[32];
    int bb = blockIdx.y;
    int tx = threadIdx.x & 31, pg = threadIdx.x >> 5;
    int q = (blockIdx.x << 5) + tx;
    const float* col = S + ((long)bb << 20) + q;
    float* oc = P + ((long)bb << 20) + q;

    float mx = -3.4e38f;
    for (int p = pg; p < 1024; p += 8) mx = fmaxf(mx, col[(long)p << 10]);
    red[pg][tx] = mx;
    __syncthreads();
    if (pg == 0) {
        float m = red[0][tx];
        #pragma unroll
        for (int r = 1; r < 8; r++) m = fmaxf(m, red[r][tx]);
        bcast[tx] = m;
    }
    __syncthreads();
    mx = bcast[tx];
    __syncthreads();

    float s = 0.f;
    for (int p = pg; p < 1024; p += 8) {
        float e = __expf(10.f * (col[(long)p << 10] - mx));
        oc[(long)p << 10] = e;
        s += e;
    }
    red[pg][tx] = s;
    __syncthreads();
    if (pg == 0) {
        float t = red[0][tx];
        #pragma unroll
        for (int r = 1; r < 8; r++) t += red[r][tx];
        bcast[tx] = 1.f / t;
    }
    __syncthreads();
    float inv = bcast[tx];
    for (int p = pg; p < 1024; p += 8) oc[(long)p << 10] *= inv;
}

// 10) transpose b: [b][c][4096] -> g_bT [b][spatial][c]
__global__ void k_transpose_b(const float* __restrict__ bsrc) {
    __shared__ float t[32][33];
    int bb = blockIdx.z;
    int s0 = blockIdx.x << 5;
    int c0 = blockIdx.y << 5;
    int x = threadIdx.x, y = threadIdx.y;
    for (int yy = y; yy < 32; yy += 8)
        t[yy][x] = bsrc[(((long)bb * CH + c0 + yy) << 12) + s0 + x];
    __syncthreads();
    for (int yy = y; yy < 32; yy += 8)
        g_bT[((((long)bb << 12) + s0 + yy) << 7) + c0 + x] = t[x][yy];
}

// 11) deconv-as-gather GEMM: z = b*4 + parity(py,px). M=128(c), N=1024, K=4096(p,dy,dx)
//     out[c, 2Y'+py, 2X'+px] = .25 * sum P[p, Y'+py-1+dy, X'+px-1+dx]
//                                    * b[c, 2hb+2-py-2dy, 2wb+2-px-2dx]
__global__ __launch_bounds__(256)
void k_gemm_deconv(const float* __restrict__ bT, const float* __restrict__ P,
                   float* __restrict__ out) {
    __shared__ float As[8][128];
    __shared__ float Bs[8][128];
    const int z = blockIdx.z;
    const int bb = z >> 2, py = (z >> 1) & 1, px = z & 1;
    const int n0 = blockIdx.x << 7;
    const int tid = threadIdx.x;
    const int lr = tid >> 5, lc = (tid & 31) << 2;
    const int tx = tid & 15, ty = tid >> 4;
    const float* Pb  = P  + ((long)bb << 20);
    const float* bTb = bT + ((long)bb << 19);

    auto loadA = [&](int k, float4& dst) {
        int p = k >> 2, dly = (k >> 1) & 1, dlx = k & 1;
        int r  = ((p >> 5) << 1) + 2 - py - (dly << 1);
        int cc = ((p & 31) << 1) + 2 - px - (dlx << 1);
        if ((unsigned)r < 64u && (unsigned)cc < 64u)
            dst = *(const float4*)(bTb + (((long)(r << 6) + cc) << 7) + lc);
        else
            dst = make_float4(0.f, 0.f, 0.f, 0.f);
    };
    auto loadB = [&](int k, float* d) {
        int p = k >> 2, dly = (k >> 1) & 1, dlx = k & 1;
        int n = n0 + lc;
        int y = (n >> 5) + py - 1 + dly;
        int Xp = n & 31;
        int xo = px - 1 + dlx;
        bool vy = (y >= 0) && (y < 32);
        #pragma unroll
        for (int j = 0; j < 4; j++) {
            int x = Xp + j + xo;
            d[j] = (vy && (unsigned)x < 32u) ? Pb[((long)p << 10) + (y << 5) + x] : 0.f;
        }
    };

    float4 ar; float brv[4];
    loadA(lr, ar);
    loadB(lr, brv);

    float acc[8][8];
    #pragma unroll
    for (int i = 0; i < 8; i++)
        #pragma unroll
        for (int j = 0; j < 8; j++) acc[i][j] = 0.f;

    for (int k0 = 0; k0 < 4096; k0 += 8) {
        *(float4*)&As[lr][lc] = ar;
        Bs[lr][lc] = brv[0]; Bs[lr][lc+1] = brv[1]; Bs[lr][lc+2] = brv[2]; Bs[lr][lc+3] = brv[3];
        __syncthreads();
        if (k0 + 8 < 4096) {
            loadA(k0 + 8 + lr, ar);
            loadB(k0 + 8 + lr, brv);
        }
        #pragma unroll
        for (int kk = 0; kk < 8; kk++) {
            float a[8], bv[8];
            *(float4*)&a[0]  = *(const float4*)&As[kk][ty << 2];
            *(float4*)&a[4]  = *(const float4*)&As[kk][64 + (ty << 2)];
            *(float4*)&bv[0] = *(const float4*)&Bs[kk][tx << 2];
            *(float4*)&bv[4] = *(const float4*)&Bs[kk][64 + (tx << 2)];
            #pragma unroll
            for (int i = 0; i < 8; i++)
                #pragma unroll
                for (int j = 0; j < 8; j++) acc[i][j] += a[i] * bv[j];
        }
        __syncthreads();
    }

    #pragma unroll
    for (int i = 0; i < 8; i++) {
        int m = ((i >> 2) << 6) + (ty << 2) + (i & 3);
        #pragma unroll
        for (int j = 0; j < 8; j++) {
            int n = n0 + ((j >> 2) << 6) + (tx << 2) + (j & 3);
            int Yp = n >> 5, Xp = n & 31;
            out[((((long)bb * CH + m) << 6) + ((Yp << 1) + py)) * 64 + (Xp << 1) + px] =
                0.25f * acc[i][j];
        }
    }
}

// 12) weight transpose: W[co][ci][3][3] -> Wt[k=(ci,i,j)][co]
__global__ void k_wt(const float* __restrict__ W) {
    int i = blockIdx.x * blockDim.x + threadIdx.x;
    if (i >= KM * CH) return;
    int co = i & 127, k = i >> 7;
    g_Wt[i] = W[(long)co * KM + k];
}

extern "C" void kernel_launch(void* const* d_in, const int* in_sizes, int n_in,
                              void* d_out, int out_size) {
    const float* f  = (const float*)d_in[0];
    const float* b  = (const float*)d_in[1];
    const float* W1 = (const float*)d_in[2];
    const float* b1 = (const float*)d_in[3];
    const float* W2 = (const float*)d_in[4];
    const float* b2 = (const float*)d_in[5];
    float* out = (float*)d_out;

    float *fd, *bd, *A, *Bm, *y1, *y2, *bT, *att, *im, *h, *Wt;
    cudaGetSymbolAddress((void**)&fd,  g_fd);
    cudaGetSymbolAddress((void**)&bd,  g_bd);
    cudaGetSymbolAddress((void**)&A,   g_A);
    cudaGetSymbolAddress((void**)&Bm,  g_Bm);
    cudaGetSymbolAddress((void**)&y1,  g_y1);
    cudaGetSymbolAddress((void**)&y2,  g_y2);
    cudaGetSymbolAddress((void**)&bT,  g_bT);
    cudaGetSymbolAddress((void**)&att, g_att);
    cudaGetSymbolAddress((void**)&im,  g_im);
    cudaGetSymbolAddress((void**)&h,   g_h);
    cudaGetSymbolAddress((void**)&Wt,  g_Wt);

    k_downsample<<<(BATCH*CH*HS*HS + 255) / 256, 256>>>(f, b);
    k_ssum<<<(BATCH*LFLAT + 255) / 256, 256>>>();
    k_norm<<<(BATCH*LFLAT + 255) / 256, 256>>>();
    k_im2col_s<<<(BATCH*KM*LFLAT + 255) / 256, 256>>>(bd, A, 1);
    k_im2col_s<<<(BATCH*KM*LFLAT + 255) / 256, 256>>>(fd, Bm, 0);

    // matching scores: y1[b][p][q]
    k_gemm<0><<<dim3(8, 8, BATCH), 256>>>(A, Bm, nullptr, y1,
        LFLAT, LFLAT, KM, (long)KM*LFLAT, (long)KM*LFLAT, (long)LFLAT*LFLAT);

    long tot = (long)BATCH * LFLAT * LFLAT;
    k_fuse1<<<(unsigned)((tot + 255) / 256), 256>>>(y1, y2);
    k_fuse2<<<(unsigned)((tot + 255) / 256), 256>>>(y2, y1);
    k_softmax<<<dim3(32, BATCH), 256>>>(y1, y2);

    k_transpose_b<<<dim3(128, 4, BATCH), dim3(32, 8)>>>(b);
    k_gemm_deconv<<<dim3(8, 1, BATCH * 4), 256>>>(bT, y2, att);

    // conv1 + ELU
    k_wt<<<(KM*CH + 255) / 256, 256>>>(W1);
    k_im2col_l<<<(BATCH*KM*NCONV + 255) / 256, 256>>>(att, im);
    k_gemm<1><<<dim3(32, 1, BATCH), 256>>>(Wt, im, b1, h,
        CH, NCONV, KM, 0L, (long)KM*NCONV, (long)CH*NCONV);

    // conv2 + ELU -> out
    k_wt<<<(KM*CH + 255) / 256, 256>>>(W2);
    k_im2col_l<<<(BATCH*KM*NCONV + 255) / 256, 256>>>(h, im);
    k_gemm<1><<<dim3(32, 1, BATCH), 256>>>(Wt, im, b2, out,
        CH, NCONV, KM, 0L, (long)KM*NCONV, (long)CH*NCONV);
}

// round 4
// speedup vs baseline: 1.0171x; 1.0171x over previous
#include <cuda_runtime.h>
#include <math.h>

#define BATCH 16
#define CH    128
#define LFLAT 1024
#define KM    1152
#define NCONV 4096

__device__ float g_fd[BATCH*CH*1024];
__device__ float g_bd[BATCH*CH*1024];
__device__ float g_ssum[BATCH*LFLAT];
__device__ float g_rnorm[BATCH*LFLAT];
__device__ float g_y1[BATCH*LFLAT*LFLAT];
__device__ float g_y2[BATCH*LFLAT*LFLAT];
__device__ float g_bT[BATCH*4096*CH];
__device__ float g_att[BATCH*CH*NCONV];
__device__ float g_h[BATCH*CH*NCONV];
__device__ float g_Wt[KM*CH];

__device__ __forceinline__ float eluf(float v) { return v > 0.f ? v : expm1f(v); }

// ---------------------------------------------------------------------------
// small prep kernels
// ---------------------------------------------------------------------------
__global__ void k_downsample(const float* __restrict__ f, const float* __restrict__ b) {
    int i = blockIdx.x * blockDim.x + threadIdx.x;
    if (i >= BATCH*CH*1024) return;
    int x = i & 31, y = (i >> 5) & 31, cb = i >> 10;
    int src = (cb << 12) + (y << 7) + (x << 1);
    g_fd[i] = f[src];
    g_bd[i] = b[src];
}

__global__ void k_ssum() {
    int i = blockIdx.x * blockDim.x + threadIdx.x;
    if (i >= BATCH*LFLAT) return;
    int bb = i >> 10, s = i & 1023;
    const float* p = g_bd + ((long)bb * CH << 10) + s;
    float a0=0, a1=0, a2=0, a3=0;
    for (int c = 0; c < CH; c += 4) {
        float v0 = p[(long)c << 10], v1 = p[(long)(c+1) << 10];
        float v2 = p[(long)(c+2) << 10], v3 = p[(long)(c+3) << 10];
        a0 += v0*v0; a1 += v1*v1; a2 += v2*v2; a3 += v3*v3;
    }
    g_ssum[i] = (a0 + a1) + (a2 + a3);
}

__global__ void k_norm() {
    int i = blockIdx.x * blockDim.x + threadIdx.x;
    if (i >= BATCH*LFLAT) return;
    int bb = i >> 10, p = i & 1023;
    int hb = p >> 5, wb = p & 31;
    float s = 0.f;
    #pragma unroll
    for (int di = -1; di <= 1; di++)
        #pragma unroll
        for (int dj = -1; dj <= 1; dj++) {
            int y = hb + di, x = wb + dj;
            if ((unsigned)y < 32u && (unsigned)x < 32u)
                s += g_ssum[(bb << 10) + (y << 5) + x];
        }
    g_rnorm[i] = 1.f / fmaxf(sqrtf(s), 1e-4f);
}

// ---------------------------------------------------------------------------
// shared FMA microkernel: 8x8 per thread from a [8][128] smem tile pair
// ---------------------------------------------------------------------------
__device__ __forceinline__ void mma_tile(const float (*As)[128], const float (*Bs)[128],
                                         float acc[8][8], int ty, int tx) {
    #pragma unroll
    for (int kk = 0; kk < 8; kk++) {
        float a[8], b[8];
        *(float4*)&a[0] = *(const float4*)&As[kk][ty << 2];
        *(float4*)&a[4] = *(const float4*)&As[kk][64 + (ty << 2)];
        *(float4*)&b[0] = *(const float4*)&Bs[kk][tx << 2];
        *(float4*)&b[4] = *(const float4*)&Bs[kk][64 + (tx << 2)];
        #pragma unroll
        for (int i = 0; i < 8; i++)
            #pragma unroll
            for (int j = 0; j < 8; j++) acc[i][j] += a[i] * b[j];
    }
}

// gather a float4 of a 3x3 im2col row (32x32 image), k=(c,di,dj), m 4-aligned
__device__ __forceinline__ float4 patch_load(const float* __restrict__ src, int k, int m,
                                             const float* __restrict__ rn) {
    int c = k / 9, t = k - c * 9;
    int q3 = t / 3;
    int di = q3 - 1, dj = t - q3 * 3 - 1;
    int y  = (m >> 5) + di;
    int x0 = (m & 31) + dj;
    float4 v = make_float4(0.f, 0.f, 0.f, 0.f);
    if ((unsigned)y < 32u) {
        const float* row = src + ((long)c << 10) + (y << 5);
        if (dj == 0) v = *(const float4*)(row + x0);
        else {
            if ((unsigned)x0     < 32u) v.x = row[x0];
            if ((unsigned)(x0+1) < 32u) v.y = row[x0+1];
            if ((unsigned)(x0+2) < 32u) v.z = row[x0+2];
            if ((unsigned)(x0+3) < 32u) v.w = row[x0+3];
        }
    }
    if (rn) {
        float4 r = *(const float4*)(rn + m);
        v.x *= r.x; v.y *= r.y; v.z *= r.z; v.w *= r.w;
    }
    return v;
}

// gather a float4 of a 3x3 im2col row (64x64 image), n 4-aligned
__device__ __forceinline__ float4 conv_load(const float* __restrict__ src, int k, int n) {
    int c = k / 9, t = k - c * 9;
    int q3 = t / 3;
    int di = q3 - 1, dj = t - q3 * 3 - 1;
    int u  = (n >> 6) + di;
    int x0 = (n & 63) + dj;
    float4 v = make_float4(0.f, 0.f, 0.f, 0.f);
    if ((unsigned)u < 64u) {
        const float* row = src + ((long)c << 12) + (u << 6);
        if (dj == 0) v = *(const float4*)(row + x0);
        else {
            if ((unsigned)x0     < 64u) v.x = row[x0];
            if ((unsigned)(x0+1) < 64u) v.y = row[x0+1];
            if ((unsigned)(x0+2) < 64u) v.z = row[x0+2];
            if ((unsigned)(x0+3) < 64u) v.w = row[x0+3];
        }
    }
    return v;
}

// ---------------------------------------------------------------------------
// matching GEMM (fused im2col both sides): y1[b][p][q] = <bd_patch(p)/||.||, fd_patch(q)>
// ---------------------------------------------------------------------------
__global__ __launch_bounds__(256)
void k_gemm_match() {
    __shared__ float As[2][8][128];
    __shared__ float Bs[2][8][128];
    const int bb = blockIdx.z;
    const float* bd_b = g_bd + ((long)bb * CH << 10);
    const float* fd_b = g_fd + ((long)bb * CH << 10);
    const float* rn_b = g_rnorm + (bb << 10);
    float* Cg = g_y1 + ((long)bb << 20);
    const int m0 = blockIdx.y << 7, n0 = blockIdx.x << 7;
    const int tid = threadIdx.x;
    const int lr = tid >> 5, lc = (tid & 31) << 2;
    const int tx = tid & 15, ty = tid >> 4;

    float acc[8][8];
    #pragma unroll
    for (int i = 0; i < 8; i++)
        #pragma unroll
        for (int j = 0; j < 8; j++) acc[i][j] = 0.f;

    float4 ar = patch_load(bd_b, lr, m0 + lc, rn_b);
    float4 br = patch_load(fd_b, lr, n0 + lc, nullptr);
    *(float4*)&As[0][lr][lc] = ar;
    *(float4*)&Bs[0][lr][lc] = br;
    __syncthreads();

    int buf = 0;
    for (int k0 = 0; k0 < KM; k0 += 8) {
        bool more = (k0 + 8 < KM);
        if (more) {
            ar = patch_load(bd_b, k0 + 8 + lr, m0 + lc, rn_b);
            br = patch_load(fd_b, k0 + 8 + lr, n0 + lc, nullptr);
        }
        mma_tile(As[buf], Bs[buf], acc, ty, tx);
        if (more) {
            *(float4*)&As[buf^1][lr][lc] = ar;
            *(float4*)&Bs[buf^1][lr][lc] = br;
        }
        __syncthreads();
        buf ^= 1;
    }

    #pragma unroll
    for (int i = 0; i < 8; i++) {
        int m = m0 + ((i >> 2) << 6) + (ty << 2) + (i & 3);
        float4 v0 = make_float4(acc[i][0], acc[i][1], acc[i][2], acc[i][3]);
        float4 v1 = make_float4(acc[i][4], acc[i][5], acc[i][6], acc[i][7]);
        *(float4*)(Cg + ((long)m << 10) + n0 + (tx << 2))      = v0;
        *(float4*)(Cg + ((long)m << 10) + n0 + 64 + (tx << 2)) = v1;
    }
}

// ---------------------------------------------------------------------------
// conv GEMM (fused im2col on B): C[co][n] = elu(sum_k Wt[k][co] * patch(src,k,n) + bias)
// ---------------------------------------------------------------------------
__global__ __launch_bounds__(256)
void k_gemm_conv(const float* __restrict__ src, const float* __restrict__ bias,
                 float* __restrict__ C) {
    __shared__ float As[2][8][128];
    __shared__ float Bs[2][8][128];
    const int bb = blockIdx.z;
    const float* src_b = src + ((long)bb * CH << 12);
    float* Cg = C + ((long)bb * CH << 12);
    const int n0 = blockIdx.x << 7;
    const int tid = threadIdx.x;
    const int lr = tid >> 5, lc = (tid & 31) << 2;
    const int tx = tid & 15, ty = tid >> 4;

    float acc[8][8];
    #pragma unroll
    for (int i = 0; i < 8; i++)
        #pragma unroll
        for (int j = 0; j < 8; j++) acc[i][j] = 0.f;

    float4 ar = *(const float4*)(g_Wt + ((long)lr << 7) + lc);
    float4 br = conv_load(src_b, lr, n0 + lc);
    *(float4*)&As[0][lr][lc] = ar;
    *(float4*)&Bs[0][lr][lc] = br;
    __syncthreads();

    int buf = 0;
    for (int k0 = 0; k0 < KM; k0 += 8) {
        bool more = (k0 + 8 < KM);
        if (more) {
            ar = *(const float4*)(g_Wt + ((long)(k0 + 8 + lr) << 7) + lc);
            br = conv_load(src_b, k0 + 8 + lr, n0 + lc);
        }
        mma_tile(As[buf], Bs[buf], acc, ty, tx);
        if (more) {
            *(float4*)&As[buf^1][lr][lc] = ar;
            *(float4*)&Bs[buf^1][lr][lc] = br;
        }
        __syncthreads();
        buf ^= 1;
    }

    #pragma unroll
    for (int i = 0; i < 8; i++) {
        int m = ((i >> 2) << 6) + (ty << 2) + (i & 3);
        float bv = bias[m];
        float4 v0, v1;
        v0.x = eluf(acc[i][0] + bv); v0.y = eluf(acc[i][1] + bv);
        v0.z = eluf(acc[i][2] + bv); v0.w = eluf(acc[i][3] + bv);
        v1.x = eluf(acc[i][4] + bv); v1.y = eluf(acc[i][5] + bv);
        v1.z = eluf(acc[i][6] + bv); v1.w = eluf(acc[i][7] + bv);
        *(float4*)(Cg + ((long)m << 12) + n0 + (tx << 2))      = v0;
        *(float4*)(Cg + ((long)m << 12) + n0 + 64 + (tx << 2)) = v1;
    }
}

// ---------------------------------------------------------------------------
// fuse + softmax
// ---------------------------------------------------------------------------
__global__ void k_fuse1(const float* __restrict__ in, float* __restrict__ out) {
    long i = (long)blockIdx.x * blockDim.x + threadIdx.x;
    if (i >= (long)BATCH*LFLAT*LFLAT) return;
    int m = i & 1023, l = (i >> 10) & 1023, bb = i >> 20;
    const float* T = in + ((long)bb << 20);
    float v = T[((long)l << 10) + m];
    if (l > 0    && m > 0)    v += T[((long)(l - 1) << 10) + (m - 1)];
    if (l < 1023 && m < 1023) v += T[((long)(l + 1) << 10) + (m + 1)];
    out[i] = v;
}

__global__ void k_fuse2(const float* __restrict__ in, float* __restrict__ out) {
    long i = (long)blockIdx.x * blockDim.x + threadIdx.x;
    if (i >= (long)BATCH*LFLAT*LFLAT) return;
    int m = i & 1023, l = (i >> 10) & 1023, bb = i >> 20;
    const float* T = in + ((long)bb << 20);
    int lt = ((l & 31) << 5) + (l >> 5);
    int mt = ((m & 31) << 5) + (m >> 5);
    float acc = 0.f;
    #pragma unroll
    for (int d = -1; d <= 1; d++) {
        int v = lt + d, w = mt + d;
        if ((unsigned)v < 1024u && (unsigned)w < 1024u) {
            int row = ((v & 31) << 5) + (v >> 5);
            int col = ((w & 31) << 5) + (w >> 5);
            acc += T[((long)row << 10) + col];
        }
    }
    out[i] = acc;
}

__global__ __launch_bounds__(256) void k_softmax(const float* __restrict__ S, float* __restrict__ P) {
    __shared__ float red[8][32];
    __shared__ float bcast[32];
    int bb = blockIdx.y;
    int tx = threadIdx.x & 31, pg = threadIdx.x >> 5;
    int q = (blockIdx.x << 5) + tx;
    const float* col = S + ((long)bb << 20) + q;
    float* oc = P + ((long)bb << 20) + q;

    float mx = -3.4e38f;
    for (int p = pg; p < 1024; p += 8) mx = fmaxf(mx, col[(long)p << 10]);
    red[pg][tx] = mx;
    __syncthreads();
    if (pg == 0) {
        float m = red[0][tx];
        #pragma unroll
        for (int r = 1; r < 8; r++) m = fmaxf(m, red[r][tx]);
        bcast[tx] = m;
    }
    __syncthreads();
    mx = bcast[tx];
    __syncthreads();

    float s = 0.f;
    for (int p = pg; p < 1024; p += 8) {
        float e = __expf(10.f * (col[(long)p << 10] - mx));
        oc[(long)p << 10] = e;
        s += e;
    }
    red[pg][tx] = s;
    __syncthreads();
    if (pg == 0) {
        float t = red[0][tx];
        #pragma unroll
        for (int r = 1; r < 8; r++) t += red[r][tx];
        bcast[tx] = 1.f / t;
    }
    __syncthreads();
    float inv = bcast[tx];
    for (int p = pg; p < 1024; p += 8) oc[(long)p << 10] *= inv;
}

// ---------------------------------------------------------------------------
// b transpose + deconv GEMM
// ---------------------------------------------------------------------------
__global__ void k_transpose_b(const float* __restrict__ bsrc) {
    __shared__ float t[32][33];
    int bb = blockIdx.z;
    int s0 = blockIdx.x << 5;
    int c0 = blockIdx.y << 5;
    int x = threadIdx.x, y = threadIdx.y;
    for (int yy = y; yy < 32; yy += 8)
        t[yy][x] = bsrc[(((long)bb * CH + c0 + yy) << 12) + s0 + x];
    __syncthreads();
    for (int yy = y; yy < 32; yy += 8)
        g_bT[((((long)bb << 12) + s0 + yy) << 7) + c0 + x] = t[x][yy];
}

__global__ __launch_bounds__(256)
void k_gemm_deconv(const float* __restrict__ bT, const float* __restrict__ P,
                   float* __restrict__ out) {
    __shared__ float As[2][8][128];
    __shared__ float Bs[2][8][128];
    const int z = blockIdx.z;
    const int bb = z >> 2, py = (z >> 1) & 1, px = z & 1;
    const int n0 = blockIdx.x << 7;
    const int tid = threadIdx.x;
    const int lr = tid >> 5, lc = (tid & 31) << 2;
    const int tx = tid & 15, ty = tid >> 4;
    const float* Pb  = P  + ((long)bb << 20);
    const float* bTb = bT + ((long)bb << 19);

    auto loadA = [&](int k, float4& dst) {
        int p = k >> 2, dly = (k >> 1) & 1, dlx = k & 1;
        int r  = ((p >> 5) << 1) + 2 - py - (dly << 1);
        int cc = ((p & 31) << 1) + 2 - px - (dlx << 1);
        if ((unsigned)r < 64u && (unsigned)cc < 64u)
            dst = *(const float4*)(bTb + (((long)(r << 6) + cc) << 7) + lc);
        else
            dst = make_float4(0.f, 0.f, 0.f, 0.f);
    };
    auto loadB = [&](int k, float* d) {
        int p = k >> 2, dly = (k >> 1) & 1, dlx = k & 1;
        int n = n0 + lc;
        int y = (n >> 5) + py - 1 + dly;
        int Xp = n & 31;
        int xo = px - 1 + dlx;
        bool vy = (y >= 0) && (y < 32);
        #pragma unroll
        for (int j = 0; j < 4; j++) {
            int x = Xp + j + xo;
            d[j] = (vy && (unsigned)x < 32u) ? Pb[((long)p << 10) + (y << 5) + x] : 0.f;
        }
    };

    float acc[8][8];
    #pragma unroll
    for (int i = 0; i < 8; i++)
        #pragma unroll
        for (int j = 0; j < 8; j++) acc[i][j] = 0.f;

    float4 ar; float brv[4];
    loadA(lr, ar);
    loadB(lr, brv);
    *(float4*)&As[0][lr][lc] = ar;
    Bs[0][lr][lc] = brv[0]; Bs[0][lr][lc+1] = brv[1];
    Bs[0][lr][lc+2] = brv[2]; Bs[0][lr][lc+3] = brv[3];
    __syncthreads();

    int buf = 0;
    for (int k0 = 0; k0 < 4096; k0 += 8) {
        bool more = (k0 + 8 < 4096);
        if (more) {
            loadA(k0 + 8 + lr, ar);
            loadB(k0 + 8 + lr, brv);
        }
        mma_tile(As[buf], Bs[buf], acc, ty, tx);
        if (more) {
            *(float4*)&As[buf^1][lr][lc] = ar;
            Bs[buf^1][lr][lc] = brv[0]; Bs[buf^1][lr][lc+1] = brv[1];
            Bs[buf^1][lr][lc+2] = brv[2]; Bs[buf^1][lr][lc+3] = brv[3];
        }
        __syncthreads();
        buf ^= 1;
    }

    #pragma unroll
    for (int i = 0; i < 8; i++) {
        int m = ((i >> 2) << 6) + (ty << 2) + (i & 3);
        #pragma unroll
        for (int j = 0; j < 8; j++) {
            int n = n0 + ((j >> 2) << 6) + (tx << 2) + (j & 3);
            int Yp = n >> 5, Xp = n & 31;
            out[((((long)bb * CH + m) << 6) + ((Yp << 1) + py)) * 64 + (Xp << 1) + px] =
                0.25f * acc[i][j];
        }
    }
}

// weight transpose: W[co][ci][3][3] -> Wt[k][co]
__global__ void k_wt(const float* __restrict__ W) {
    int i = blockIdx.x * blockDim.x + threadIdx.x;
    if (i >= KM * CH) return;
    int co = i & 127, k = i >> 7;
    g_Wt[i] = W[(long)co * KM + k];
}

extern "C" void kernel_launch(void* const* d_in, const int* in_sizes, int n_in,
                              void* d_out, int out_size) {
    const float* f  = (const float*)d_in[0];
    const float* b  = (const float*)d_in[1];
    const float* W1 = (const float*)d_in[2];
    const float* b1 = (const float*)d_in[3];
    const float* W2 = (const float*)d_in[4];
    const float* b2 = (const float*)d_in[5];
    float* out = (float*)d_out;

    float *y1, *y2, *bT, *att, *h;
    cudaGetSymbolAddress((void**)&y1,  g_y1);
    cudaGetSymbolAddress((void**)&y2,  g_y2);
    cudaGetSymbolAddress((void**)&bT,  g_bT);
    cudaGetSymbolAddress((void**)&att, g_att);
    cudaGetSymbolAddress((void**)&h,   g_h);

    k_downsample<<<(BATCH*CH*1024 + 255) / 256, 256>>>(f, b);
    k_ssum<<<(BATCH*LFLAT + 255) / 256, 256>>>();
    k_norm<<<(BATCH*LFLAT + 255) / 256, 256>>>();

    // matching scores (im2col fused into loaders)
    k_gemm_match<<<dim3(8, 8, BATCH), 256>>>();

    long tot = (long)BATCH * LFLAT * LFLAT;
    k_fuse1<<<(unsigned)((tot + 255) / 256), 256>>>(y1, y2);
    k_fuse2<<<(unsigned)((tot + 255) / 256), 256>>>(y2, y1);
    k_softmax<<<dim3(32, BATCH), 256>>>(y1, y2);

    k_transpose_b<<<dim3(128, 4, BATCH), dim3(32, 8)>>>(b);
    k_gemm_deconv<<<dim3(8, 1, BATCH * 4), 256>>>(bT, y2, att);

    // conv1 + ELU (im2col fused)
    k_wt<<<(KM*CH + 255) / 256, 256>>>(W1);
    k_gemm_conv<<<dim3(32, 1, BATCH), 256>>>(att, b1, h);

    // conv2 + ELU -> out
    k_wt<<<(KM*CH + 255) / 256, 256>>>(W2);
    k_gemm_conv<<<dim3(32, 1, BATCH), 256>>>(h, b2, out);
}

// round 8
// speedup vs baseline: 1.3216x; 1.2994x over previous
#include <cuda_runtime.h>
#include <cuda_bf16.h>
#include <math.h>
#include <stdint.h>

#define BATCH 16
#define CH    128
#define LFLAT 1024
#define KM    1152
#define NCONV 4096

// ---------------------------------------------------------------------------
// scratch
// ---------------------------------------------------------------------------
__device__ float g_fd[BATCH*CH*1024];
__device__ float g_bd[BATCH*CH*1024];
__device__ float g_ssum[BATCH*LFLAT];
__device__ float g_rnorm[BATCH*LFLAT];
__device__ float g_y1[BATCH*LFLAT*LFLAT];
__device__ float g_y2[BATCH*LFLAT*LFLAT];
__device__ float g_bT[BATCH*4096*CH];
__device__ float g_att[BATCH*CH*NCONV];
__device__ float g_h[BATCH*CH*NCONV];
__device__ float g_Wt[KM*CH];

__device__ __forceinline__ float eluf(float v) { return v > 0.f ? v : expm1f(v); }

__device__ __forceinline__ uint32_t smem_u32(const void* p) {
    uint32_t a;
    asm("{ .reg .u64 t; cvta.to.shared.u64 t, %1; cvt.u32.u64 %0, t; }" : "=r"(a) : "l"(p));
    return a;
}

#define LDMATRIX_X4(r0, r1, r2, r3, addr) \
    asm volatile("ldmatrix.sync.aligned.m8n8.x4.shared.b16 {%0,%1,%2,%3}, [%4];" \
        : "=r"(r0), "=r"(r1), "=r"(r2), "=r"(r3) : "r"(addr))
#define LDMATRIX_X2(r0, r1, addr) \
    asm volatile("ldmatrix.sync.aligned.m8n8.x2.shared.b16 {%0,%1}, [%2];" \
        : "=r"(r0), "=r"(r1) : "r"(addr))
#define MMA_BF16(c, a, b) \
    asm volatile("mma.sync.aligned.m16n8k16.row.col.f32.bf16.bf16.f32 " \
        "{%0,%1,%2,%3}, {%4,%5,%6,%7}, {%8,%9}, {%0,%1,%2,%3};" \
        : "+f"((c)[0]), "+f"((c)[1]), "+f"((c)[2]), "+f"((c)[3]) \
        : "r"((a)[0]), "r"((a)[1]), "r"((a)[2]), "r"((a)[3]), "r"((b)[0]), "r"((b)[1]))

// fp32 -> bf16 hi/lo split, packed as bf16x2 (even k in low half)
__device__ __forceinline__ uint32_t pack2(__nv_bfloat16 a, __nv_bfloat16 b) {
    __nv_bfloat162 t; t.x = a; t.y = b;
    return *reinterpret_cast<uint32_t*>(&t);
}
__device__ __forceinline__ void split2(float v0, float v1, uint32_t& hi, uint32_t& lo) {
    __nv_bfloat16 h0 = __float2bfloat16(v0), h1 = __float2bfloat16(v1);
    __nv_bfloat16 l0 = __float2bfloat16(v0 - __bfloat162float(h0));
    __nv_bfloat16 l1 = __float2bfloat16(v1 - __bfloat162float(h1));
    hi = pack2(h0, h1); lo = pack2(l0, l1);
}

// ---------------------------------------------------------------------------
// operand gathers (fused im2col / deconv gathers), fp32
// MODE 0: matching  A=bd patches (*rnorm), B=fd patches, K=1152
// MODE 1: conv      A=Wt[k][co],           B=3x3 patches of 64x64 img, K=1152
// MODE 2: deconv    A=bT gather,           B=P gather, K=4096
// ---------------------------------------------------------------------------
template<int MODE>
__device__ __forceinline__ float loadA(const float* __restrict__ src, int k, int m,
                                       int py, int px) {
    if (MODE == 0) {
        int c = k / 9, t = k - c * 9;
        int q3 = t / 3, di = q3 - 1, dj = t - q3 * 3 - 1;
        int y = (m >> 5) + di, x = (m & 31) + dj;
        if ((unsigned)y < 32u && (unsigned)x < 32u)
            return src[((long)c << 10) + (y << 5) + x];
        return 0.f;
    } else if (MODE == 1) {
        return src[((long)k << 7) + m];
    } else {
        int p = k >> 2, dly = (k >> 1) & 1, dlx = k & 1;
        int r  = ((p >> 5) << 1) + 2 - py - (dly << 1);
        int cc = ((p & 31) << 1) + 2 - px - (dlx << 1);
        if ((unsigned)r < 64u && (unsigned)cc < 64u)
            return src[(((long)(r << 6) + cc) << 7) + m];
        return 0.f;
    }
}
template<int MODE>
__device__ __forceinline__ float loadB(const float* __restrict__ src, int k, int n,
                                       int py, int px) {
    if (MODE == 0) {
        int c = k / 9, t = k - c * 9;
        int q3 = t / 3, di = q3 - 1, dj = t - q3 * 3 - 1;
        int y = (n >> 5) + di, x = (n & 31) + dj;
        if ((unsigned)y < 32u && (unsigned)x < 32u)
            return src[((long)c << 10) + (y << 5) + x];
        return 0.f;
    } else if (MODE == 1) {
        int c = k / 9, t = k - c * 9;
        int q3 = t / 3, di = q3 - 1, dj = t - q3 * 3 - 1;
        int u = (n >> 6) + di, x = (n & 63) + dj;
        if ((unsigned)u < 64u && (unsigned)x < 64u)
            return src[((long)c << 12) + (u << 6) + x];
        return 0.f;
    } else {
        int p = k >> 2, dly = (k >> 1) & 1, dlx = k & 1;
        int y = (n >> 5) + py - 1 + dly;
        int x = (n & 31) + px - 1 + dlx;
        if ((unsigned)y < 32u && (unsigned)x < 32u)
            return src[((long)p << 10) + (y << 5) + x];
        return 0.f;
    }
}

// ---------------------------------------------------------------------------
// mma.sync GEMM: CTA 128x128, BK=32, 8 warps (4 along M x 2 along N; 32x64/warp)
// bf16 hi/lo split: D += Ah*Bh + Ah*Bl + Al*Bh  (fp32 accumulate)
// ---------------------------------------------------------------------------
template<int MODE>
__global__ __launch_bounds__(256)
void k_mma_gemm(const float* __restrict__ pA, const float* __restrict__ pB,
                const float* __restrict__ bias, float* __restrict__ pC) {
    constexpr int NCH = (MODE == 2) ? 128 : 36;   // K / 32
    __shared__ __align__(16) __nv_bfloat16 sA[2][128][40];  // [hi/lo][m][k] pad 40
    __shared__ __align__(16) __nv_bfloat16 sB[2][128][40];  // [hi/lo][n][k]

    const int tid = threadIdx.x;
    const int wid = tid >> 5;
    const int lane = tid & 31;

    int bb, py = 0, px = 0, m0 = 0;
    if (MODE == 2) { int z = blockIdx.z; bb = z >> 2; py = (z >> 1) & 1; px = z & 1; }
    else bb = blockIdx.z;
    if (MODE == 0) m0 = blockIdx.y << 7;
    const int n0 = blockIdx.x << 7;

    const float* Asrc; const float* Bsrc; const float* rn = nullptr;
    if (MODE == 0) {
        Asrc = g_bd + ((long)bb * CH << 10);
        Bsrc = g_fd + ((long)bb * CH << 10);
        rn   = g_rnorm + (bb << 10);
    } else if (MODE == 1) {
        Asrc = pA;
        Bsrc = pB + ((long)bb * CH << 12);
    } else {
        Asrc = pA + ((long)bb << 19);
        Bsrc = pB + ((long)bb << 20);
    }

    // producer indices: 2 threads per row, 16-k halves
    const int prow = tid >> 1;
    const int pkh  = (tid & 1) << 4;
    float rnv = 1.f;
    if (MODE == 0) rnv = rn[m0 + prow];

    // mma indices
    const int wm = (wid & 3) << 5;   // 0,32,64,96
    const int wn = (wid >> 2) << 6;  // 0,64
    const int a_r = lane & 15, a_c = (lane >> 4) << 3;
    const int b_r = lane & 7,  b_c = ((lane >> 3) & 1) << 3;

    float acc[2][8][4];
    #pragma unroll
    for (int mf = 0; mf < 2; mf++)
        #pragma unroll
        for (int nf = 0; nf < 8; nf++)
            #pragma unroll
            for (int r = 0; r < 4; r++) acc[mf][nf][r] = 0.f;

    for (int ch = 0; ch < NCH; ch++) {
        const int kbase = ch * 32 + pkh;
        // ---- produce A ----
        {
            float v[16];
            #pragma unroll
            for (int j = 0; j < 16; j++)
                v[j] = loadA<MODE>(Asrc, kbase + j, m0 + prow, py, px) * rnv;
            #pragma unroll
            for (int j = 0; j < 8; j++) {
                uint32_t hi, lo;
                split2(v[2*j], v[2*j+1], hi, lo);
                *(uint32_t*)&sA[0][prow][pkh + 2*j] = hi;
                *(uint32_t*)&sA[1][prow][pkh + 2*j] = lo;
            }
        }
        // ---- produce B ----
        {
            float v[16];
            #pragma unroll
            for (int j = 0; j < 16; j++)
                v[j] = loadB<MODE>(Bsrc, kbase + j, n0 + prow, py, px);
            #pragma unroll
            for (int j = 0; j < 8; j++) {
                uint32_t hi, lo;
                split2(v[2*j], v[2*j+1], hi, lo);
                *(uint32_t*)&sB[0][prow][pkh + 2*j] = hi;
                *(uint32_t*)&sB[1][prow][pkh + 2*j] = lo;
            }
        }
        __syncthreads();

        // ---- mma: 2 k-steps of 16 ----
        #pragma unroll
        for (int ks = 0; ks < 2; ks++) {
            const int k0 = ks << 4;
            uint32_t ah[2][4], al[2][4];
            #pragma unroll
            for (int mf = 0; mf < 2; mf++) {
                LDMATRIX_X4(ah[mf][0], ah[mf][1], ah[mf][2], ah[mf][3],
                            smem_u32(&sA[0][wm + (mf << 4) + a_r][k0 + a_c]));
                LDMATRIX_X4(al[mf][0], al[mf][1], al[mf][2], al[mf][3],
                            smem_u32(&sA[1][wm + (mf << 4) + a_r][k0 + a_c]));
            }
            uint32_t bh[8][2], bl[8][2];
            #pragma unroll
            for (int nf = 0; nf < 8; nf++) {
                LDMATRIX_X2(bh[nf][0], bh[nf][1],
                            smem_u32(&sB[0][wn + (nf << 3) + b_r][k0 + b_c]));
                LDMATRIX_X2(bl[nf][0], bl[nf][1],
                            smem_u32(&sB[1][wn + (nf << 3) + b_r][k0 + b_c]));
            }
            #pragma unroll
            for (int mf = 0; mf < 2; mf++)
                #pragma unroll
                for (int nf = 0; nf < 8; nf++) {
                    MMA_BF16(acc[mf][nf], ah[mf], bh[nf]);
                    MMA_BF16(acc[mf][nf], ah[mf], bl[nf]);
                    MMA_BF16(acc[mf][nf], al[mf], bh[nf]);
                }
        }
        __syncthreads();
    }

    // ---- epilogue ----
    const int g = lane >> 2, tig = lane & 3;
    #pragma unroll
    for (int mf = 0; mf < 2; mf++) {
        #pragma unroll
        for (int p = 0; p < 2; p++) {
            const int row = wm + (mf << 4) + g + (p << 3);
            #pragma unroll
            for (int nf = 0; nf < 8; nf++) {
                const float c0 = acc[mf][nf][2*p], c1 = acc[mf][nf][2*p + 1];
                const int col = wn + (nf << 3) + (tig << 1);
                if (MODE == 0) {
                    float2 o = make_float2(c0, c1);
                    *(float2*)(g_y1 + ((long)bb << 20) + ((long)(m0 + row) << 10) + n0 + col) = o;
                } else if (MODE == 1) {
                    const float bv = bias[row];
                    float2 o = make_float2(eluf(c0 + bv), eluf(c1 + bv));
                    *(float2*)(pC + ((long)bb * CH << 12) + ((long)row << 12) + n0 + col) = o;
                } else {
                    float* ob = pC + ((long)bb * CH << 12) + ((long)row << 12);
                    int n = n0 + col;
                    int Yp = n >> 5, Xp = n & 31;
                    ob[(((Yp << 1) + py) << 6) + (Xp << 1) + px] = 0.25f * c0;
                    n++;
                    Yp = n >> 5; Xp = n & 31;
                    ob[(((Yp << 1) + py) << 6) + (Xp << 1) + px] = 0.25f * c1;
                }
            }
        }
    }
}

// ---------------------------------------------------------------------------
// prep + elementwise kernels (unchanged, validated)
// ---------------------------------------------------------------------------
__global__ void k_downsample(const float* __restrict__ f, const float* __restrict__ b) {
    int i = blockIdx.x * blockDim.x + threadIdx.x;
    if (i >= BATCH*CH*1024) return;
    int x = i & 31, y = (i >> 5) & 31, cb = i >> 10;
    int src = (cb << 12) + (y << 7) + (x << 1);
    g_fd[i] = f[src];
    g_bd[i] = b[src];
}

__global__ void k_ssum() {
    int i = blockIdx.x * blockDim.x + threadIdx.x;
    if (i >= BATCH*LFLAT) return;
    int bb = i >> 10, s = i & 1023;
    const float* p = g_bd + ((long)bb * CH << 10) + s;
    float a0=0, a1=0, a2=0, a3=0;
    for (int c = 0; c < CH; c += 4) {
        float v0 = p[(long)c << 10], v1 = p[(long)(c+1) << 10];
        float v2 = p[(long)(c+2) << 10], v3 = p[(long)(c+3) << 10];
        a0 += v0*v0; a1 += v1*v1; a2 += v2*v2; a3 += v3*v3;
    }
    g_ssum[i] = (a0 + a1) + (a2 + a3);
}

__global__ void k_norm() {
    int i = blockIdx.x * blockDim.x + threadIdx.x;
    if (i >= BATCH*LFLAT) return;
    int bb = i >> 10, p = i & 1023;
    int hb = p >> 5, wb = p & 31;
    float s = 0.f;
    #pragma unroll
    for (int di = -1; di <= 1; di++)
        #pragma unroll
        for (int dj = -1; dj <= 1; dj++) {
            int y = hb + di, x = wb + dj;
            if ((unsigned)y < 32u && (unsigned)x < 32u)
                s += g_ssum[(bb << 10) + (y << 5) + x];
        }
    g_rnorm[i] = 1.f / fmaxf(sqrtf(s), 1e-4f);
}

__global__ void k_fuse1(const float* __restrict__ in, float* __restrict__ out) {
    long i = (long)blockIdx.x * blockDim.x + threadIdx.x;
    if (i >= (long)BATCH*LFLAT*LFLAT) return;
    int m = i & 1023, l = (i >> 10) & 1023, bb = i >> 20;
    const float* T = in + ((long)bb << 20);
    float v = T[((long)l << 10) + m];
    if (l > 0    && m > 0)    v += T[((long)(l - 1) << 10) + (m - 1)];
    if (l < 1023 && m < 1023) v += T[((long)(l + 1) << 10) + (m + 1)];
    out[i] = v;
}

__global__ void k_fuse2(const float* __restrict__ in, float* __restrict__ out) {
    long i = (long)blockIdx.x * blockDim.x + threadIdx.x;
    if (i >= (long)BATCH*LFLAT*LFLAT) return;
    int m = i & 1023, l = (i >> 10) & 1023, bb = i >> 20;
    const float* T = in + ((long)bb << 20);
    int lt = ((l & 31) << 5) + (l >> 5);
    int mt = ((m & 31) << 5) + (m >> 5);
    float acc = 0.f;
    #pragma unroll
    for (int d = -1; d <= 1; d++) {
        int v = lt + d, w = mt + d;
        if ((unsigned)v < 1024u && (unsigned)w < 1024u) {
            int row = ((v & 31) << 5) + (v >> 5);
            int col = ((w & 31) << 5) + (w >> 5);
            acc += T[((long)row << 10) + col];
        }
    }
    out[i] = acc;
}

__global__ __launch_bounds__(256) void k_softmax(const float* __restrict__ S, float* __restrict__ P) {
    __shared__ float red[8][32];
    __shared__ float bcast[32];
    int bb = blockIdx.y;
    int tx = threadIdx.x & 31, pg = threadIdx.x >> 5;
    int q = (blockIdx.x << 5) + tx;
    const float* col = S + ((long)bb << 20) + q;
    float* oc = P + ((long)bb << 20) + q;

    float mx = -3.4e38f;
    for (int p = pg; p < 1024; p += 8) mx = fmaxf(mx, col[(long)p << 10]);
    red[pg][tx] = mx;
    __syncthreads();
    if (pg == 0) {
        float m = red[0][tx];
        #pragma unroll
        for (int r = 1; r < 8; r++) m = fmaxf(m, red[r][tx]);
        bcast[tx] = m;
    }
    __syncthreads();
    mx = bcast[tx];
    __syncthreads();

    float s = 0.f;
    for (int p = pg; p < 1024; p += 8) {
        float e = __expf(10.f * (col[(long)p << 10] - mx));
        oc[(long)p << 10] = e;
        s += e;
    }
    red[pg][tx] = s;
    __syncthreads();
    if (pg == 0) {
        float t = red[0][tx];
        #pragma unroll
        for (int r = 1; r < 8; r++) t += red[r][tx];
        bcast[tx] = 1.f / t;
    }
    __syncthreads();
    float inv = bcast[tx];
    for (int p = pg; p < 1024; p += 8) oc[(long)p << 10] *= inv;
}

__global__ void k_transpose_b(const float* __restrict__ bsrc) {
    __shared__ float t[32][33];
    int bb = blockIdx.z;
    int s0 = blockIdx.x << 5;
    int c0 = blockIdx.y << 5;
    int x = threadIdx.x, y = threadIdx.y;
    for (int yy = y; yy < 32; yy += 8)
        t[yy][x] = bsrc[(((long)bb * CH + c0 + yy) << 12) + s0 + x];
    __syncthreads();
    for (int yy = y; yy < 32; yy += 8)
        g_bT[((((long)bb << 12) + s0 + yy) << 7) + c0 + x] = t[x][yy];
}

__global__ void k_wt(const float* __restrict__ W) {
    int i = blockIdx.x * blockDim.x + threadIdx.x;
    if (i >= KM * CH) return;
    int co = i & 127, k = i >> 7;
    g_Wt[i] = W[(long)co * KM + k];
}

// ---------------------------------------------------------------------------
extern "C" void kernel_launch(void* const* d_in, const int* in_sizes, int n_in,
                              void* d_out, int out_size) {
    const float* f  = (const float*)d_in[0];
    const float* b  = (const float*)d_in[1];
    const float* W1 = (const float*)d_in[2];
    const float* b1 = (const float*)d_in[3];
    const float* W2 = (const float*)d_in[4];
    const float* b2 = (const float*)d_in[5];
    float* out = (float*)d_out;

    float *y1, *y2, *bT, *att, *h, *Wt;
    cudaGetSymbolAddress((void**)&y1,  g_y1);
    cudaGetSymbolAddress((void**)&y2,  g_y2);
    cudaGetSymbolAddress((void**)&bT,  g_bT);
    cudaGetSymbolAddress((void**)&att, g_att);
    cudaGetSymbolAddress((void**)&h,   g_h);
    cudaGetSymbolAddress((void**)&Wt,  g_Wt);

    k_downsample<<<(BATCH*CH*1024 + 255) / 256, 256>>>(f, b);
    k_ssum<<<(BATCH*LFLAT + 255) / 256, 256>>>();
    k_norm<<<(BATCH*LFLAT + 255) / 256, 256>>>();

    // matching scores -> y1
    k_mma_gemm<0><<<dim3(8, 8, BATCH), 256>>>(nullptr, nullptr, nullptr, nullptr);

    long tot = (long)BATCH * LFLAT * LFLAT;
    k_fuse1<<<(unsigned)((tot + 255) / 256), 256>>>(y1, y2);
    k_fuse2<<<(unsigned)((tot + 255) / 256), 256>>>(y2, y1);
    k_softmax<<<dim3(32, BATCH), 256>>>(y1, y2);

    k_transpose_b<<<dim3(128, 4, BATCH), dim3(32, 8)>>>(b);
    // deconv -> att   (z = batch*4 parity classes)
    k_mma_gemm<2><<<dim3(8, 1, BATCH * 4), 256>>>(bT, y2, nullptr, att);

    // conv1 + ELU -> h
    k_wt<<<(KM*CH + 255) / 256, 256>>>(W1);
    k_mma_gemm<1><<<dim3(32, 1, BATCH), 256>>>(Wt, att, b1, h);

    // conv2 + ELU -> out
    k_wt<<<(KM*CH + 255) / 256, 256>>>(W2);
    k_mma_gemm<1><<<dim3(32, 1, BATCH), 256>>>(Wt, h, b2, out);
}